// round 2
// baseline (speedup 1.0000x reference)
#include <cuda_runtime.h>
#include <cuda_bf16.h>
#include <math.h>

// Problem constants
#define BATCH 64
#define LSEQ  48
#define EDIM  300
#define F0DIM 300
#define NEGV  (-1000000000.0f)

// Kernel B tiling
#define TI 16
#define TJ 16
#define KC 24          // K-chunk (600 = 25 * 24)
#define NF 64          // f per CTA (5 chunks cover 300, last partial)
#define RSTR 308       // smem row stride for r tiles (float4-aligned, conflict-lite)
#define WSTR 68        // smem row stride for w chunk

// Scratch (device globals: allowed; BSS zero-init, deterministic)
__device__ float g_R[128 * LSEQ * EDIM];            // r1 (s=0..63), r2 (s=64..127)
__device__ float g_P[2 * BATCH * 3 * LSEQ * F0DIM]; // s1/s2 partial maxes per tile
__device__ float g_H[BATCH * 600];                  // pooled [h1 | h2]

// ---------------------------------------------------------------------------
// Kernel A: embedding gather + conv1d(k=3, pad=1) + tanh  -> g_R
// grid (128, 4): x = sequence id (0..63 q1, 64..127 q2), y = l-tile of 12
// ---------------------------------------------------------------------------
__global__ __launch_bounds__(320) void encode_kernel(
    const int* __restrict__ q1, const int* __restrict__ q2,
    const int* __restrict__ q1_len, const int* __restrict__ q2_len,
    const float* __restrict__ emb, const float* __restrict__ conv_w,
    const float* __restrict__ conv_b)
{
    int s = blockIdx.x;
    int b = s & 63;
    bool side = s >= 64;
    int len = side ? q2_len[b] : q1_len[b];
    int lt = blockIdx.y * 12;
    if (lt >= len) return;

    extern __shared__ float sm[];
    float* xs = sm;                       // [50][300], rows 0 and 49 are zero pad
    int* toks = (int*)(xs + 50 * 300);    // [48]
    const int* q = side ? q2 : q1;
    int tid = threadIdx.x;

    if (tid < 48) toks[tid] = q[b * 48 + tid];
    for (int e = tid; e < 300; e += blockDim.x) {
        xs[e] = 0.f;
        xs[49 * 300 + e] = 0.f;
    }
    __syncthreads();

    // gather emb rows (float4 coalesced)
    for (int i = tid; i < 48 * 75; i += blockDim.x) {
        int l = i / 75, c = i - l * 75;
        const float4* src = (const float4*)(emb + (size_t)toks[l] * 300);
        ((float4*)(xs + (l + 1) * 300))[c] = src[c];
    }
    __syncthreads();

    if (tid < 300) {
        int eo = tid;
        const float* w = conv_w + eo * 900;
        float acc[12];
        #pragma unroll
        for (int t = 0; t < 12; t++) acc[t] = 0.f;

        for (int ei = 0; ei < 300; ei++) {
            float w0 = w[ei * 3 + 0];
            float w1 = w[ei * 3 + 1];
            float w2 = w[ei * 3 + 2];
            float xa = xs[(lt + 0) * 300 + ei];
            float xb = xs[(lt + 1) * 300 + ei];
            #pragma unroll
            for (int t = 0; t < 12; t++) {
                float xc = xs[(lt + t + 2) * 300 + ei];
                acc[t] += w0 * xa + w1 * xb + w2 * xc;
                xa = xb; xb = xc;
            }
        }
        float bi = conv_b[eo];
        int nl = min(12, len - lt);
        for (int t = 0; t < nl; t++)
            g_R[(size_t)(s * 48 + lt + t) * 300 + eo] = tanhf(acc[t] + bi);
    }
}

// ---------------------------------------------------------------------------
// Kernel B: fused joint GEMM + masked max partials.
// grid (15, 3, 64): x = it*5+fc, y = jt, z = b. 256 threads.
// C-tile = 256 pairs x 64 f ; K = 600 (d-features then p-features).
// ---------------------------------------------------------------------------
__global__ __launch_bounds__(256) void joint_kernel(
    const float* __restrict__ fc0_w, const float* __restrict__ fc0_b,
    const int* __restrict__ q1_len, const int* __restrict__ q2_len)
{
    int b  = blockIdx.z;
    int jt = blockIdx.y;
    int it = blockIdx.x / 5;
    int fc = blockIdx.x % 5;
    int l1 = q1_len[b], l2 = q2_len[b];
    if (it * TI >= l1 || jt * TJ >= l2) return;

    extern __shared__ float sm[];
    float* r1s  = sm;                     // [16][RSTR]
    float* r2s  = r1s + TI * RSTR;        // [16][RSTR]
    float* feat = r2s + TJ * RSTR;        // [KC][256]
    float* ws   = feat + KC * 256;        // [KC][WSTR]

    int tid = threadIdx.x;
    int lane = tid & 31, warp = tid >> 5;

    // load r tiles (float4): 16 rows x 300 each
    {
        const float4* R1g = (const float4*)(g_R + (size_t)(b * LSEQ + it * TI) * EDIM);
        const float4* R2g = (const float4*)(g_R + (size_t)((BATCH + b) * LSEQ + jt * TJ) * EDIM);
        for (int i = tid; i < TI * 75; i += 256) {
            int row = i / 75, c = i - row * 75;
            ((float4*)(r1s + row * RSTR))[c] = R1g[row * 75 + c];
            ((float4*)(r2s + row * RSTR))[c] = R2g[row * 75 + c];
        }
    }

    int f0 = fc * NF;
    float acc[8][8];
    #pragma unroll
    for (int i = 0; i < 8; i++)
        #pragma unroll
        for (int j = 0; j < 8; j++) acc[i][j] = 0.f;

    int iloc = tid >> 4, jloc = tid & 15;
    const float* r1row = r1s + iloc * RSTR;
    const float* r2row = r2s + jloc * RSTR;

    for (int kc0 = 0; kc0 < 600; kc0 += KC) {
        __syncthreads();
        // stage weight chunk: ws[kk][fo] = fc0_w[f0+fo][kc0+kk] (0 for f>=300)
        for (int i = tid; i < KC * NF; i += 256) {
            int kk = i % KC, fo = i / KC;
            int f = f0 + fo;
            ws[kk * WSTR + fo] = (f < F0DIM) ? fc0_w[(size_t)f * 600 + kc0 + kk] : 0.f;
        }
        // stage feature chunk: feat[kk][pair]
        if (kc0 + KC <= 300) {
            #pragma unroll
            for (int kk = 0; kk < KC; kk++) {
                int e = kc0 + kk;
                feat[kk * 256 + tid] = fabsf(r1row[e] - r2row[e]);
            }
        } else if (kc0 >= 300) {
            #pragma unroll
            for (int kk = 0; kk < KC; kk++) {
                int e = kc0 - 300 + kk;
                feat[kk * 256 + tid] = r1row[e] * r2row[e];
            }
        } else {
            for (int kk = 0; kk < KC; kk++) {
                int kg = kc0 + kk;
                float v = (kg < 300) ? fabsf(r1row[kg] - r2row[kg])
                                     : r1row[kg - 300] * r2row[kg - 300];
                feat[kk * 256 + tid] = v;
            }
        }
        __syncthreads();

        #pragma unroll 4
        for (int kk = 0; kk < KC; kk++) {
            float4 a0 = *(const float4*)(feat + kk * 256 + lane * 8);
            float4 a1 = *(const float4*)(feat + kk * 256 + lane * 8 + 4);
            float4 b0 = *(const float4*)(ws + kk * WSTR + warp * 8);
            float4 b1 = *(const float4*)(ws + kk * WSTR + warp * 8 + 4);
            float a[8] = {a0.x, a0.y, a0.z, a0.w, a1.x, a1.y, a1.z, a1.w};
            float bb[8] = {b0.x, b0.y, b0.z, b0.w, b1.x, b1.y, b1.z, b1.w};
            #pragma unroll
            for (int mi = 0; mi < 8; mi++)
                #pragma unroll
                for (int ni = 0; ni < 8; ni++)
                    acc[mi][ni] += a[mi] * bb[ni];
        }
    }

    // Epilogue. pair m = lane*8+mi -> i = lane>>1, j = (lane&1)*8+mi
    int iglob = it * TI + (lane >> 1);
    int g = lane & 1;
    int fbase = f0 + warp * 8;

    // s1 partial: max over valid j of this tile (bias+tanh after max; monotone)
    {
        int jrem = l2 - (jt * TJ + g * 8); // valid count in this 8-j half
        float jm[8];
        #pragma unroll
        for (int ni = 0; ni < 8; ni++) {
            float v = NEGV;
            #pragma unroll
            for (int mi = 0; mi < 8; mi++)
                if (mi < jrem) v = fmaxf(v, acc[mi][ni]);
            v = fmaxf(v, __shfl_xor_sync(0xffffffffu, v, 1));
            jm[ni] = v;
        }
        if (g == 0 && iglob < l1) {
            float* P0 = g_P + ((size_t)(0 * BATCH + b) * 3 + jt) * (LSEQ * F0DIM) + iglob * F0DIM;
            #pragma unroll
            for (int ni = 0; ni < 8; ni++) {
                int f = fbase + ni;
                if (f < F0DIM) P0[f] = tanhf(jm[ni] + fc0_b[f]);
            }
        }
    }
    // s2 partial: max over valid i of this tile (butterfly over lanes stride 2)
    {
        bool iv = iglob < l1;
        #pragma unroll
        for (int mi = 0; mi < 8; mi++)
            #pragma unroll
            for (int ni = 0; ni < 8; ni++) {
                float v = iv ? acc[mi][ni] : NEGV;
                v = fmaxf(v, __shfl_xor_sync(0xffffffffu, v, 2));
                v = fmaxf(v, __shfl_xor_sync(0xffffffffu, v, 4));
                v = fmaxf(v, __shfl_xor_sync(0xffffffffu, v, 8));
                v = fmaxf(v, __shfl_xor_sync(0xffffffffu, v, 16));
                acc[mi][ni] = v;
            }
        if (lane < 2) {
            float* P1 = g_P + ((size_t)(BATCH + b) * 3 + it) * (LSEQ * F0DIM);
            #pragma unroll
            for (int mi = 0; mi < 8; mi++) {
                int jg = jt * TJ + lane * 8 + mi;
                if (jg < l2) {
                    #pragma unroll
                    for (int ni = 0; ni < 8; ni++) {
                        int f = fbase + ni;
                        if (f < F0DIM) P1[jg * F0DIM + f] = tanhf(acc[mi][ni] + fc0_b[f]);
                    }
                }
            }
        }
    }
}

// ---------------------------------------------------------------------------
// Kernel C: reduce partials -> s ; attention logits + softmax ; h -> g_H
// grid (2, 64): x = side (0: pool over s1/r1, 1: s2/r2), y = b. 256 threads.
// ---------------------------------------------------------------------------
__global__ __launch_bounds__(256) void pool_kernel(
    const int* __restrict__ q1_len, const int* __restrict__ q2_len,
    const float* __restrict__ att_w, const float* __restrict__ att_b)
{
    int side = blockIdx.x, b = blockIdx.y;
    int l1 = q1_len[b], l2 = q2_len[b];
    int len  = side ? l2 : l1;    // own sequence length
    int olen = side ? l1 : l2;    // other length (tile count for partials)
    int ntiles = (olen + 15) >> 4;

    extern __shared__ float sm[];
    float* sv = sm;               // [48][301]
    float* lg = sv + 48 * 301;    // [48] logits -> softmax weights
    int tid = threadIdx.x;

    const float* P = g_P + (size_t)(side * BATCH + b) * 3 * (LSEQ * F0DIM);
    for (int idx = tid; idx < len * 300; idx += 256) {
        int l = idx / 300, f = idx - l * 300;
        float v = P[l * 300 + f];
        for (int t = 1; t < ntiles; t++)
            v = fmaxf(v, P[(size_t)t * (LSEQ * F0DIM) + l * 300 + f]);
        sv[l * 301 + f] = v;
    }
    __syncthreads();

    int lane = tid & 31, warp = tid >> 5;
    const float* Rbase = g_R + (size_t)(side * BATCH + b) * 48 * 300;
    for (int l = warp; l < len; l += 8) {
        float a = 0.f;
        for (int e = lane; e < 300; e += 32) {
            a += att_w[e]       * Rbase[l * 300 + e];
            a += att_w[300 + e] * sv[l * 301 + e];
        }
        #pragma unroll
        for (int d = 16; d; d >>= 1) a += __shfl_xor_sync(0xffffffffu, a, d);
        if (lane == 0) lg[l] = a + att_b[0];
    }
    __syncthreads();

    if (warp == 0) {
        float v0 = (lane < len) ? lg[lane] : NEGV;
        float v1 = (lane + 32 < len) ? lg[lane + 32] : NEGV;
        float mx = fmaxf(v0, v1);
        #pragma unroll
        for (int d = 16; d; d >>= 1) mx = fmaxf(mx, __shfl_xor_sync(0xffffffffu, mx, d));
        float e0 = (lane < len) ? expf(v0 - mx) : 0.f;
        float e1 = (lane + 32 < len) ? expf(v1 - mx) : 0.f;
        float s = e0 + e1;
        #pragma unroll
        for (int d = 16; d; d >>= 1) s += __shfl_xor_sync(0xffffffffu, s, d);
        float inv = 1.f / s;
        if (lane < len) lg[lane] = e0 * inv;
        if (lane + 32 < len) lg[lane + 32] = e1 * inv;
    }
    __syncthreads();

    // FIX (R1): was `if (tid < 300)` with only 256 threads -> features 256..299
    // of h were never written (stayed zero). Strided loop covers all 300.
    for (int f = tid; f < 300; f += 256) {
        float h = 0.f;
        for (int l = 0; l < len; l++) h += lg[l] * sv[l * 301 + f];
        g_H[b * 600 + side * 300 + f] = h;
    }
}

// ---------------------------------------------------------------------------
// Kernel D: j = tanh(H @ fc1_w^T + b) ; out = j @ fc2_w^T + b. grid 64.
// ---------------------------------------------------------------------------
__global__ __launch_bounds__(320) void head_kernel(
    const float* __restrict__ fc1_w, const float* __restrict__ fc1_b,
    const float* __restrict__ fc2_w, const float* __restrict__ fc2_b,
    float* __restrict__ out)
{
    __shared__ float Hs[600];
    __shared__ float jv[300];
    int b = blockIdx.x, tid = threadIdx.x;
    for (int i = tid; i < 600; i += blockDim.x) Hs[i] = g_H[b * 600 + i];
    __syncthreads();
    if (tid < 300) {
        const float* w = fc1_w + (size_t)tid * 600;
        float acc = 0.f;
        for (int k = 0; k < 600; k++) acc += Hs[k] * w[k];
        jv[tid] = tanhf(acc + fc1_b[tid]);
    }
    __syncthreads();
    int warp = tid >> 5, lane = tid & 31;
    if (warp < 2) {
        float acc = 0.f;
        for (int f = lane; f < 300; f += 32) acc += jv[f] * fc2_w[warp * 300 + f];
        #pragma unroll
        for (int d = 16; d; d >>= 1) acc += __shfl_xor_sync(0xffffffffu, acc, d);
        if (lane == 0) out[b * 2 + warp] = acc + fc2_b[warp];
    }
}

// ---------------------------------------------------------------------------
extern "C" void kernel_launch(void* const* d_in, const int* in_sizes, int n_in,
                              void* d_out, int out_size)
{
    const int*   q1     = (const int*)d_in[0];
    const int*   q2     = (const int*)d_in[1];
    const int*   q1_len = (const int*)d_in[2];
    const int*   q2_len = (const int*)d_in[3];
    const float* emb    = (const float*)d_in[4];
    const float* conv_w = (const float*)d_in[5];
    const float* conv_b = (const float*)d_in[6];
    const float* fc0_w  = (const float*)d_in[7];
    const float* fc0_b  = (const float*)d_in[8];
    const float* fc1_w  = (const float*)d_in[9];
    const float* fc1_b  = (const float*)d_in[10];
    const float* fc2_w  = (const float*)d_in[11];
    const float* fc2_b  = (const float*)d_in[12];
    const float* att_w  = (const float*)d_in[13];
    const float* att_b  = (const float*)d_in[14];
    float* out = (float*)d_out;

    const int smA = 50 * 300 * 4 + 48 * 4;                       // 60192
    const int smB = (TI + TJ) * RSTR * 4 + KC * 256 * 4 + KC * WSTR * 4; // 70528
    const int smC = 48 * 301 * 4 + 48 * 4;                       // 57984

    cudaFuncSetAttribute(encode_kernel, cudaFuncAttributeMaxDynamicSharedMemorySize, smA);
    cudaFuncSetAttribute(joint_kernel,  cudaFuncAttributeMaxDynamicSharedMemorySize, smB);
    cudaFuncSetAttribute(pool_kernel,   cudaFuncAttributeMaxDynamicSharedMemorySize, smC);

    encode_kernel<<<dim3(128, 4), 320, smA>>>(q1, q2, q1_len, q2_len, emb, conv_w, conv_b);
    joint_kernel<<<dim3(15, 3, 64), 256, smB>>>(fc0_w, fc0_b, q1_len, q2_len);
    pool_kernel<<<dim3(2, 64), 256, smC>>>(q1_len, q2_len, att_w, att_b);
    head_kernel<<<64, 320>>>(fc1_w, fc1_b, fc2_w, fc2_b, out);
    (void)in_sizes; (void)n_in; (void)out_size;
}

// round 4
// speedup vs baseline: 1.6369x; 1.6369x over previous
#include <cuda_runtime.h>
#include <cuda_fp16.h>
#include <cstdint>
#include <math.h>

#define BATCH 64
#define LSEQ  48
#define EDIM  300
#define F0DIM 300
#define NEGV  (-1000000000.0f)

// ---------------- helpers ----------------
__device__ __forceinline__ uint32_t smem_u32(const void* p) {
    uint32_t a;
    asm("{ .reg .u64 t; cvta.to.shared.u64 t, %1; cvt.u32.u64 %0, t; }"
        : "=r"(a) : "l"(p));
    return a;
}
#define LDSM4(r, addr) \
    asm volatile("ldmatrix.sync.aligned.m8n8.x4.shared.b16 {%0,%1,%2,%3}, [%4];" \
        : "=r"((r)[0]), "=r"((r)[1]), "=r"((r)[2]), "=r"((r)[3]) : "r"(addr))
#define LDSM2(r, addr) \
    asm volatile("ldmatrix.sync.aligned.m8n8.x2.shared.b16 {%0,%1}, [%2];" \
        : "=r"((r)[0]), "=r"((r)[1]) : "r"(addr))
#define MMA16816(c, a, bb) \
    asm volatile("mma.sync.aligned.m16n8k16.row.col.f32.f16.f16.f32 " \
        "{%0,%1,%2,%3}, {%4,%5,%6,%7}, {%8,%9}, {%0,%1,%2,%3};" \
        : "+f"((c)[0]), "+f"((c)[1]), "+f"((c)[2]), "+f"((c)[3]) \
        : "r"((a)[0]), "r"((a)[1]), "r"((a)[2]), "r"((a)[3]), \
          "r"((bb)[0]), "r"((bb)[1]))

// ---------------- global scratch ----------------
__device__ float g_R[128 * LSEQ * EDIM];            // r1 (0..63), r2 (64..127)
__device__ float g_P1[64 * 3 * 48 * 304];           // s1 tile-partials [b][jt][i][f]
__device__ float g_P2[64 * 6 * 48 * 304];           // s2 tile-partials [b][it][j][f]
__device__ float g_H[64 * 600];
__device__ float g_J[64 * 300];
// weights, fp16 hi/lo split, layout [fc(3)][chunk(10)][n(112)][k(64)]
__device__ uint4 g_W4h[3 * 10 * 112 * 64 / 8];
__device__ uint4 g_W4l[3 * 10 * 112 * 64 / 8];

// ---------------------------------------------------------------------------
// prep_w: fp32 fc0_w -> fp16 hi/lo split in CTA-chunk layout
// grid (30, 112) block 64: x = fc*10+c, y = n, tid = k
// ---------------------------------------------------------------------------
__global__ void prep_w(const float* __restrict__ fc0_w) {
    int fcc = blockIdx.x;           // fc*10 + c
    int fc = fcc / 10, c = fcc % 10;
    int n = blockIdx.y, k = threadIdx.x;
    int f = fc * 112 + n;
    int kg = c * 64 + k;
    float v = (f < 300 && kg < 600) ? fc0_w[(size_t)f * 600 + kg] : 0.f;
    __half h = __float2half_rn(v);
    __half l = __float2half_rn(v - __half2float(h));
    size_t idx = ((size_t)fcc * 112 + n) * 64 + k;
    ((__half*)g_W4h)[idx] = h;
    ((__half*)g_W4l)[idx] = l;
}

// ---------------------------------------------------------------------------
// Kernel A: embedding gather + conv1d(k=3, pad=1) + tanh -> g_R
// ---------------------------------------------------------------------------
__global__ __launch_bounds__(320) void encode_kernel(
    const int* __restrict__ q1, const int* __restrict__ q2,
    const int* __restrict__ q1_len, const int* __restrict__ q2_len,
    const float* __restrict__ emb, const float* __restrict__ conv_w,
    const float* __restrict__ conv_b)
{
    int s = blockIdx.x;
    int b = s & 63;
    bool side = s >= 64;
    int len = side ? q2_len[b] : q1_len[b];
    int lt = blockIdx.y * 12;
    if (lt >= len) return;

    extern __shared__ float sm[];
    float* xs = sm;                       // [50][300] rows 0/49 zero pad
    int* toks = (int*)(xs + 50 * 300);
    const int* q = side ? q2 : q1;
    int tid = threadIdx.x;

    if (tid < 48) toks[tid] = q[b * 48 + tid];
    for (int e = tid; e < 300; e += blockDim.x) { xs[e] = 0.f; xs[49 * 300 + e] = 0.f; }
    __syncthreads();
    for (int i = tid; i < 48 * 75; i += blockDim.x) {
        int l = i / 75, c = i - l * 75;
        const float4* src = (const float4*)(emb + (size_t)toks[l] * 300);
        ((float4*)(xs + (l + 1) * 300))[c] = src[c];
    }
    __syncthreads();
    if (tid < 300) {
        int eo = tid;
        const float* w = conv_w + eo * 900;
        float acc[12];
        #pragma unroll
        for (int t = 0; t < 12; t++) acc[t] = 0.f;
        for (int ei = 0; ei < 300; ei++) {
            float w0 = w[ei * 3 + 0], w1 = w[ei * 3 + 1], w2 = w[ei * 3 + 2];
            float xa = xs[(lt + 0) * 300 + ei];
            float xb = xs[(lt + 1) * 300 + ei];
            #pragma unroll
            for (int t = 0; t < 12; t++) {
                float xc = xs[(lt + t + 2) * 300 + ei];
                acc[t] += w0 * xa + w1 * xb + w2 * xc;
                xa = xb; xb = xc;
            }
        }
        float bi = conv_b[eo];
        int nl = min(12, len - lt);
        for (int t = 0; t < nl; t++)
            g_R[(size_t)(s * 48 + lt + t) * 300 + eo] = tanhf(acc[t] + bi);
    }
}

// ---------------------------------------------------------------------------
// joint_tc: HMMA fp16 3-term split fused joint GEMM + masked max partials.
// grid (18, 3, 64): x = it*3 + fc, y = jt, z = b. 256 threads (8 warps 4Mx2N).
// CTA tile: M=128 pairs (8 i x 16 j), N=112 f, K=640 (10 chunks of 64).
// D = Ahi*Bhi + Alo*Bhi + Ahi*Blo  (fp16 split, fp32 acc; err ~2^-22)
// ---------------------------------------------------------------------------
#define AST 72     // smem A row stride (halves)
#define BST 72     // smem B row stride (halves)
#define JST 116    // smem J row stride (floats)
#define OF_BH 0
#define OF_BL 16384
#define OF_AH 32768
#define OF_AL 51200
#define OF_R1 69632
#define OF_R2 79360
#define SMB_TOTAL 98816

__global__ __launch_bounds__(256) void joint_tc(
    const int* __restrict__ q1_len, const int* __restrict__ q2_len,
    const float* __restrict__ fc0_b)
{
    int xf = blockIdx.x;
    int it = xf / 3, fc = xf % 3;
    int jt = blockIdx.y, b = blockIdx.z;
    int l1 = q1_len[b], l2 = q2_len[b];
    if (it * 8 >= l1 || jt * 16 >= l2) return;

    extern __shared__ char smc[];
    __half* sBh = (__half*)(smc + OF_BH);
    __half* sBl = (__half*)(smc + OF_BL);
    __half* sAh = (__half*)(smc + OF_AH);
    __half* sAl = (__half*)(smc + OF_AL);
    float* r1s = (float*)(smc + OF_R1);   // [8][304]
    float* r2s = (float*)(smc + OF_R2);   // [16][304]
    float* smJ = (float*)smc;             // [128][JST] (epilogue, overlaps A/B)

    int tid = threadIdx.x;
    int warp = tid >> 5, lane = tid & 31;
    int nw = warp & 1, mw = warp >> 1;

    // stage r tiles (fp32)
    {
        const float4* R1 = (const float4*)(g_R + (size_t)(b * 48 + it * 8) * 300);
        const float4* R2 = (const float4*)(g_R + (size_t)((64 + b) * 48 + jt * 16) * 300);
        for (int i = tid; i < 8 * 75; i += 256) {
            int r = i / 75, c = i - r * 75;
            ((float4*)(r1s + r * 304))[c] = R1[r * 75 + c];
        }
        for (int i = tid; i < 16 * 75; i += 256) {
            int r = i / 75, c = i - r * 75;
            ((float4*)(r2s + r * 304))[c] = R2[r * 75 + c];
        }
    }

    float acc[2][7][4];
    #pragma unroll
    for (int mi = 0; mi < 2; mi++)
        #pragma unroll
        for (int ni = 0; ni < 7; ni++)
            #pragma unroll
            for (int v = 0; v < 4; v++) acc[mi][ni][v] = 0.f;

    // ldmatrix base addresses
    uint32_t sbase = smem_u32(smc);
    int arow = mw * 32 + (lane & 15);
    int acol = (lane >> 4) << 3;
    uint32_t aAh0 = sbase + OF_AH + (uint32_t)(arow * AST + acol) * 2;
    uint32_t aAh1 = aAh0 + 16 * AST * 2;
    uint32_t aAl0 = sbase + OF_AL + (uint32_t)(arow * AST + acol) * 2;
    uint32_t aAl1 = aAl0 + 16 * AST * 2;
    int brow = nw * 56 + (lane & 7);
    int bcol = lane & 8;
    uint32_t aBh = sbase + OF_BH + (uint32_t)(brow * BST + bcol) * 2;
    uint32_t aBl = sbase + OF_BL + (uint32_t)(brow * BST + bcol) * 2;

    // feature staging mapping: thread -> (pair p, k-half)
    int fp_ = tid >> 1, fhalf = tid & 1;
    const float* r1p = r1s + (fp_ >> 4) * 304;
    const float* r2p = r2s + (fp_ & 15) * 304;
    __half2* fdh = (__half2*)(sAh + fp_ * AST + fhalf * 32);
    __half2* fdl = (__half2*)(sAl + fp_ * AST + fhalf * 32);

    for (int c = 0; c < 10; c++) {
        __syncthreads();
        // copy weight chunk hi+lo (straight uint4 copies, pre-laid-out)
        {
            const uint4* srch = g_W4h + (size_t)(fc * 10 + c) * 896;
            const uint4* srcl = g_W4l + (size_t)(fc * 10 + c) * 896;
            for (int i = tid; i < 896; i += 256) {
                int n = i >> 3, kk = i & 7;
                *(uint4*)(sBh + n * BST + kk * 8) = srch[i];
                *(uint4*)(sBl + n * BST + kk * 8) = srcl[i];
            }
        }
        // build feature chunk hi+lo
        {
            int kb = c * 64 + fhalf * 32;
            #pragma unroll
            for (int m = 0; m < 16; m++) {
                int e = kb + 2 * m;
                float v0, v1;
                if (e < 300)      { v0 = fabsf(r1p[e] - r2p[e]);     v1 = fabsf(r1p[e + 1] - r2p[e + 1]); }
                else if (e < 600) { v0 = r1p[e - 300] * r2p[e - 300]; v1 = r1p[e - 299] * r2p[e - 299]; }
                else              { v0 = 0.f; v1 = 0.f; }
                __half h0 = __float2half_rn(v0), h1 = __float2half_rn(v1);
                fdh[m] = __halves2half2(h0, h1);
                fdl[m] = __halves2half2(__float2half_rn(v0 - __half2float(h0)),
                                        __float2half_rn(v1 - __half2float(h1)));
            }
        }
        __syncthreads();

        #pragma unroll
        for (int ks = 0; ks < 4; ks++) {
            uint32_t k2 = (uint32_t)(ks * 16) * 2;
            uint32_t ah[2][4], al[2][4], bh[7][2], bl[7][2];
            LDSM4(ah[0], aAh0 + k2);
            LDSM4(ah[1], aAh1 + k2);
            #pragma unroll
            for (int n8 = 0; n8 < 7; n8++) LDSM2(bh[n8], aBh + (uint32_t)(n8 * 8 * BST) * 2 + k2);
            #pragma unroll
            for (int mi = 0; mi < 2; mi++)
                #pragma unroll
                for (int ni = 0; ni < 7; ni++) MMA16816(acc[mi][ni], ah[mi], bh[ni]);
            LDSM4(al[0], aAl0 + k2);
            LDSM4(al[1], aAl1 + k2);
            #pragma unroll
            for (int mi = 0; mi < 2; mi++)
                #pragma unroll
                for (int ni = 0; ni < 7; ni++) MMA16816(acc[mi][ni], al[mi], bh[ni]);
            #pragma unroll
            for (int n8 = 0; n8 < 7; n8++) LDSM2(bl[n8], aBl + (uint32_t)(n8 * 8 * BST) * 2 + k2);
            #pragma unroll
            for (int mi = 0; mi < 2; mi++)
                #pragma unroll
                for (int ni = 0; ni < 7; ni++) MMA16816(acc[mi][ni], ah[mi], bl[ni]);
        }
    }
    __syncthreads();  // A/B smem dead; reuse as smJ

    // write accumulators to smJ [128 pairs][112 f]
    {
        int r0 = mw * 32 + (lane >> 2);
        int c0 = nw * 56 + (lane & 3) * 2;
        #pragma unroll
        for (int mi = 0; mi < 2; mi++)
            #pragma unroll
            for (int ni = 0; ni < 7; ni++) {
                int r = r0 + mi * 16, cc = c0 + ni * 8;
                smJ[r * JST + cc]           = acc[mi][ni][0];
                smJ[r * JST + cc + 1]       = acc[mi][ni][1];
                smJ[(r + 8) * JST + cc]     = acc[mi][ni][2];
                smJ[(r + 8) * JST + cc + 1] = acc[mi][ni][3];
            }
    }
    __syncthreads();

    // masked max + bias + tanh -> tile partials
    int fbase = fc * 112;
    int flim = min(112, 300 - fbase);
    int icnt = min(8, l1 - it * 8);
    int jcnt = min(16, l2 - jt * 16);

    for (int idx = tid; idx < icnt * flim; idx += 256) {
        int i = idx / flim, f = idx - i * flim;
        float v = smJ[(i * 16) * JST + f];
        for (int j = 1; j < jcnt; j++) v = fmaxf(v, smJ[(i * 16 + j) * JST + f]);
        int ig = it * 8 + i, fg = fbase + f;
        g_P1[((size_t)(b * 3 + jt) * 48 + ig) * 304 + fg] = tanhf(v + fc0_b[fg]);
    }
    for (int idx = tid; idx < jcnt * flim; idx += 256) {
        int j = idx / flim, f = idx - j * flim;
        float v = smJ[j * JST + f];
        for (int i = 1; i < icnt; i++) v = fmaxf(v, smJ[(i * 16 + j) * JST + f]);
        int jg = jt * 16 + j, fg = fbase + f;
        g_P2[((size_t)(b * 6 + it) * 48 + jg) * 304 + fg] = tanhf(v + fc0_b[fg]);
    }
}

// ---------------------------------------------------------------------------
// pool: reduce tile partials -> s ; attention softmax ; h -> g_H
// grid (2, 64). 256 threads.
// ---------------------------------------------------------------------------
__global__ __launch_bounds__(256) void pool_kernel(
    const int* __restrict__ q1_len, const int* __restrict__ q2_len,
    const float* __restrict__ att_w, const float* __restrict__ att_b)
{
    int side = blockIdx.x, b = blockIdx.y;
    int l1 = q1_len[b], l2 = q2_len[b];
    int len = side ? l2 : l1;
    int nt  = side ? ((l1 + 7) >> 3) : ((l2 + 15) >> 4);
    const float* Pb = side ? (g_P2 + (size_t)b * 6 * 48 * 304)
                           : (g_P1 + (size_t)b * 3 * 48 * 304);

    extern __shared__ float sm[];
    float* sv = sm;              // [48][301]
    float* lg = sv + 48 * 301;   // [48]
    int tid = threadIdx.x;

    for (int idx = tid; idx < len * 300; idx += 256) {
        int l = idx / 300, f = idx - l * 300;
        float v = Pb[(size_t)l * 304 + f];
        for (int t = 1; t < nt; t++)
            v = fmaxf(v, Pb[(size_t)t * 48 * 304 + (size_t)l * 304 + f]);
        sv[l * 301 + f] = v;
    }
    __syncthreads();

    int lane = tid & 31, warp = tid >> 5;
    const float* Rbase = g_R + (size_t)(side * 64 + b) * 48 * 300;
    for (int l = warp; l < len; l += 8) {
        float a = 0.f;
        for (int e = lane; e < 300; e += 32) {
            a += att_w[e]       * Rbase[l * 300 + e];
            a += att_w[300 + e] * sv[l * 301 + e];
        }
        #pragma unroll
        for (int d = 16; d; d >>= 1) a += __shfl_xor_sync(0xffffffffu, a, d);
        if (lane == 0) lg[l] = a + att_b[0];
    }
    __syncthreads();

    if (warp == 0) {
        float v0 = (lane < len) ? lg[lane] : NEGV;
        float v1 = (lane + 32 < len) ? lg[lane + 32] : NEGV;
        float mx = fmaxf(v0, v1);
        #pragma unroll
        for (int d = 16; d; d >>= 1) mx = fmaxf(mx, __shfl_xor_sync(0xffffffffu, mx, d));
        float e0 = (lane < len) ? expf(v0 - mx) : 0.f;
        float e1 = (lane + 32 < len) ? expf(v1 - mx) : 0.f;
        float s = e0 + e1;
        #pragma unroll
        for (int d = 16; d; d >>= 1) s += __shfl_xor_sync(0xffffffffu, s, d);
        float inv = 1.f / s;
        if (lane < len) lg[lane] = e0 * inv;
        if (lane + 32 < len) lg[lane + 32] = e1 * inv;
    }
    __syncthreads();

    for (int f = tid; f < 300; f += 256) {
        float h = 0.f;
        for (int l = 0; l < len; l++) h += lg[l] * sv[l * 301 + f];
        g_H[b * 600 + side * 300 + f] = h;
    }
}

// ---------------------------------------------------------------------------
// head1: jv = tanh(H @ fc1_w^T + b). grid (64, 5), block 256.
// ---------------------------------------------------------------------------
__global__ __launch_bounds__(256) void head1_kernel(
    const float* __restrict__ fc1_w, const float* __restrict__ fc1_b)
{
    __shared__ float Hs[600];
    __shared__ float part[256];
    int b = blockIdx.x, fb = blockIdx.y;
    int tid = threadIdx.x;
    for (int i = tid; i < 600; i += 256) Hs[i] = g_H[b * 600 + i];
    __syncthreads();
    int fl = tid >> 2, seg = tid & 3;
    int f = fb * 60 + fl;
    float acc = 0.f;
    if (fl < 60) {
        const float* w = fc1_w + (size_t)f * 600 + seg * 150;
        const float* h = Hs + seg * 150;
        #pragma unroll 6
        for (int k = 0; k < 150; k++) acc += h[k] * w[k];
    }
    part[tid] = acc;
    __syncthreads();
    if (seg == 0 && fl < 60) {
        float s = part[tid] + part[tid + 1] + part[tid + 2] + part[tid + 3];
        g_J[b * 300 + f] = tanhf(s + fc1_b[f]);
    }
}

// head2: out = jv @ fc2_w^T + b. grid 64, block 64.
__global__ __launch_bounds__(64) void head2_kernel(
    const float* __restrict__ fc2_w, const float* __restrict__ fc2_b,
    float* __restrict__ out)
{
    int b = blockIdx.x, tid = threadIdx.x;
    int c = tid >> 5, lane = tid & 31;
    float acc = 0.f;
    for (int f = lane; f < 300; f += 32)
        acc += g_J[b * 300 + f] * fc2_w[c * 300 + f];
    #pragma unroll
    for (int d = 16; d; d >>= 1) acc += __shfl_xor_sync(0xffffffffu, acc, d);
    if (lane == 0) out[b * 2 + c] = acc + fc2_b[c];
}

// ---------------------------------------------------------------------------
extern "C" void kernel_launch(void* const* d_in, const int* in_sizes, int n_in,
                              void* d_out, int out_size)
{
    const int*   q1     = (const int*)d_in[0];
    const int*   q2     = (const int*)d_in[1];
    const int*   q1_len = (const int*)d_in[2];
    const int*   q2_len = (const int*)d_in[3];
    const float* emb    = (const float*)d_in[4];
    const float* conv_w = (const float*)d_in[5];
    const float* conv_b = (const float*)d_in[6];
    const float* fc0_w  = (const float*)d_in[7];
    const float* fc0_b  = (const float*)d_in[8];
    const float* fc1_w  = (const float*)d_in[9];
    const float* fc1_b  = (const float*)d_in[10];
    const float* fc2_w  = (const float*)d_in[11];
    const float* fc2_b  = (const float*)d_in[12];
    const float* att_w  = (const float*)d_in[13];
    const float* att_b  = (const float*)d_in[14];
    float* out = (float*)d_out;

    const int smA = 50 * 300 * 4 + 48 * 4;
    const int smC = 48 * 301 * 4 + 48 * 4;

    cudaFuncSetAttribute(encode_kernel, cudaFuncAttributeMaxDynamicSharedMemorySize, smA);
    cudaFuncSetAttribute(joint_tc,      cudaFuncAttributeMaxDynamicSharedMemorySize, SMB_TOTAL);
    cudaFuncSetAttribute(pool_kernel,   cudaFuncAttributeMaxDynamicSharedMemorySize, smC);

    prep_w<<<dim3(30, 112), 64>>>(fc0_w);
    encode_kernel<<<dim3(128, 4), 320, smA>>>(q1, q2, q1_len, q2_len, emb, conv_w, conv_b);
    joint_tc<<<dim3(18, 3, 64), 256, SMB_TOTAL>>>(q1_len, q2_len, fc0_b);
    pool_kernel<<<dim3(2, 64), 256, smC>>>(q1_len, q2_len, att_w, att_b);
    head1_kernel<<<dim3(64, 5), 256>>>(fc1_w, fc1_b);
    head2_kernel<<<64, 64>>>(fc2_w, fc2_b, out);
    (void)in_sizes; (void)n_in; (void)out_size;
}

// round 6
// speedup vs baseline: 2.2810x; 1.3935x over previous
#include <cuda_runtime.h>
#include <cuda_fp16.h>
#include <cstdint>
#include <math.h>

#define BATCH 64
#define LSEQ  48
#define EDIM  300
#define F0DIM 300
#define NEGV  (-1000000000.0f)

// ---------------- helpers ----------------
__device__ __forceinline__ uint32_t smem_u32(const void* p) {
    uint32_t a;
    asm("{ .reg .u64 t; cvta.to.shared.u64 t, %1; cvt.u32.u64 %0, t; }"
        : "=r"(a) : "l"(p));
    return a;
}
#define LDSM4(r, addr) \
    asm volatile("ldmatrix.sync.aligned.m8n8.x4.shared.b16 {%0,%1,%2,%3}, [%4];" \
        : "=r"((r)[0]), "=r"((r)[1]), "=r"((r)[2]), "=r"((r)[3]) : "r"(addr))
#define LDSM2(r, addr) \
    asm volatile("ldmatrix.sync.aligned.m8n8.x2.shared.b16 {%0,%1}, [%2];" \
        : "=r"((r)[0]), "=r"((r)[1]) : "r"(addr))
#define MMA16816(c, a, bb) \
    asm volatile("mma.sync.aligned.m16n8k16.row.col.f32.f16.f16.f32 " \
        "{%0,%1,%2,%3}, {%4,%5,%6,%7}, {%8,%9}, {%0,%1,%2,%3};" \
        : "+f"((c)[0]), "+f"((c)[1]), "+f"((c)[2]), "+f"((c)[3]) \
        : "r"((a)[0]), "r"((a)[1]), "r"((a)[2]), "r"((a)[3]), \
          "r"((bb)[0]), "r"((bb)[1]))

// order-preserving float<->uint for atomic max
__device__ __forceinline__ unsigned enc_f(float x) {
    unsigned u = __float_as_uint(x);
    return (u & 0x80000000u) ? ~u : (u | 0x80000000u);
}
__device__ __forceinline__ float dec_f(unsigned k) {
    unsigned u = (k & 0x80000000u) ? (k & 0x7fffffffu) : ~k;
    return __uint_as_float(u);
}

// ---------------- global scratch ----------------
__device__ float g_R[128 * LSEQ * EDIM];            // r1 (0..63), r2 (64..127)
__device__ unsigned g_Su[2 * 64 * 48 * 304];        // s1 | s2 encoded max (pre-tanh)
__device__ float g_H[64 * 600];
__device__ float g_J[64 * 300];
// fc0 weights, fp16 hi/lo split, layout [fc(3)][chunk(10)][n(112)][k(64)]
__device__ uint4 g_W4h[3 * 10 * 112 * 64 / 8];
__device__ uint4 g_W4l[3 * 10 * 112 * 64 / 8];
// conv weights, fp16 hi/lo, layout [t(3)][n(320)][k(320)]
__device__ __half g_CWh[3 * 320 * 320];
__device__ __half g_CWl[3 * 320 * 320];

#define S2_OFF (64 * 48 * 304)   // 933888

// ---------------------------------------------------------------------------
// prep_w: fc0_w -> fp16 hi/lo split in joint CTA-chunk layout
// ---------------------------------------------------------------------------
__global__ void prep_w(const float* __restrict__ fc0_w) {
    int fcc = blockIdx.x;           // fc*10 + c
    int fc = fcc / 10, c = fcc % 10;
    int n = blockIdx.y, k = threadIdx.x;
    int f = fc * 112 + n;
    int kg = c * 64 + k;
    float v = (f < 300 && kg < 600) ? fc0_w[(size_t)f * 600 + kg] : 0.f;
    __half h = __float2half_rn(v);
    __half l = __float2half_rn(v - __half2float(h));
    size_t idx = ((size_t)fcc * 112 + n) * 64 + k;
    ((__half*)g_W4h)[idx] = h;
    ((__half*)g_W4l)[idx] = l;
}

// prep_cw: conv_w (E,E,3) -> W_t[n=eo][k=ei] fp16 hi/lo, zero-padded to 320x320
__global__ void prep_cw(const float* __restrict__ conv_w) {
    int t = blockIdx.x, n = blockIdx.y, k = threadIdx.x;
    float v = (n < 300 && k < 300) ? conv_w[(size_t)n * 900 + k * 3 + t] : 0.f;
    __half h = __float2half_rn(v);
    __half l = __float2half_rn(v - __half2float(h));
    size_t idx = ((size_t)t * 320 + n) * 320 + k;
    g_CWh[idx] = h;
    g_CWl[idx] = l;
}

// init_s: seed encoded NEG
__global__ void init_s() {
    unsigned idx = blockIdx.x * 256 + threadIdx.x;
    if (idx < 2u * S2_OFF) g_Su[idx] = ~__float_as_uint(NEGV);
}

// ---------------------------------------------------------------------------
// encode_tc: HMMA conv1d.  y = tanh(sum_t shift_t(X) @ W_t^T + b)
// grid (128, 2): x = s, y = nh (eo half of 160). 192 threads (3M x 2N warps).
// ---------------------------------------------------------------------------
#define XSTR 328
#define EBST 72
#define OF_XH 0
#define OF_XL 32800
#define OF_EBH 65600
#define OF_EBL 88640
#define OF_TOK 111680
#define SME_TOTAL 111872

__global__ __launch_bounds__(192) void encode_tc(
    const int* __restrict__ q1, const int* __restrict__ q2,
    const float* __restrict__ emb, const float* __restrict__ conv_b)
{
    int s = blockIdx.x, nh = blockIdx.y;
    int b = s & 63;
    bool side = s >= 64;
    extern __shared__ char smc[];
    __half* xh = (__half*)(smc + OF_XH);   // [50][XSTR], row r = x[r-1]
    __half* xl = (__half*)(smc + OF_XL);
    __half* sbh = (__half*)(smc + OF_EBH); // [160][EBST]
    __half* sbl = (__half*)(smc + OF_EBL);
    int* toks = (int*)(smc + OF_TOK);
    int tid = threadIdx.x, warp = tid >> 5, lane = tid & 31;
    const int* q = side ? q2 : q1;

    if (tid < 48) toks[tid] = q[b * 48 + tid];
    for (int i = tid; i < 4100; i += 192) ((uint4*)smc)[i] = make_uint4(0, 0, 0, 0);
    __syncthreads();
    for (int i = tid; i < 48 * 300; i += 192) {
        int l = i / 300, ei = i - l * 300;
        float v = emb[(size_t)toks[l] * 300 + ei];
        __half h = __float2half_rn(v);
        xh[(l + 1) * XSTR + ei] = h;
        xl[(l + 1) * XSTR + ei] = __float2half_rn(v - __half2float(h));
    }

    int mw = warp >> 1, nw = warp & 1;
    float acc[10][4];
    #pragma unroll
    for (int n8 = 0; n8 < 10; n8++)
        #pragma unroll
        for (int v = 0; v < 4; v++) acc[n8][v] = 0.f;

    uint32_t sbase = smem_u32(smc);
    uint32_t aXh = sbase + OF_XH + (uint32_t)((mw * 16 + (lane & 15)) * XSTR + ((lane >> 4) << 3)) * 2;
    uint32_t aXl = aXh + (OF_XL - OF_XH);
    // FIX (R5): B-fragment row base must include this warp's n-tile (nw*80).
    uint32_t aBh = sbase + OF_EBH + (uint32_t)((nw * 80 + (lane & 7)) * EBST + (lane & 8)) * 2;
    uint32_t aBl = aBh + (OF_EBL - OF_EBH);

    for (int t = 0; t < 3; t++) {
        const __half* gwh = g_CWh + ((size_t)t * 320 + nh * 160) * 320;
        const __half* gwl = g_CWl + ((size_t)t * 320 + nh * 160) * 320;
        for (int c = 0; c < 5; c++) {
            __syncthreads();
            {
                const uint4* sh = (const uint4*)(gwh + c * 64);
                const uint4* sl = (const uint4*)(gwl + c * 64);
                for (int i = tid; i < 160 * 8; i += 192) {
                    int n = i >> 3, kk = i & 7;
                    *(uint4*)(sbh + n * EBST + kk * 8) = sh[n * 40 + kk];
                    *(uint4*)(sbl + n * EBST + kk * 8) = sl[n * 40 + kk];
                }
            }
            __syncthreads();
            uint32_t aoff = (uint32_t)(t * XSTR + c * 64) * 2;
            #pragma unroll
            for (int ks = 0; ks < 4; ks++) {
                uint32_t k2 = ks * 32;
                uint32_t ah[4], al[4], bhf[10][2], blf[10][2];
                LDSM4(ah, aXh + aoff + k2);
                LDSM4(al, aXl + aoff + k2);
                #pragma unroll
                for (int n8 = 0; n8 < 10; n8++) LDSM2(bhf[n8], aBh + (uint32_t)(n8 * 8 * EBST) * 2 + k2);
                #pragma unroll
                for (int n8 = 0; n8 < 10; n8++) MMA16816(acc[n8], ah, bhf[n8]);
                #pragma unroll
                for (int n8 = 0; n8 < 10; n8++) MMA16816(acc[n8], al, bhf[n8]);
                #pragma unroll
                for (int n8 = 0; n8 < 10; n8++) LDSM2(blf[n8], aBl + (uint32_t)(n8 * 8 * EBST) * 2 + k2);
                #pragma unroll
                for (int n8 = 0; n8 < 10; n8++) MMA16816(acc[n8], ah, blf[n8]);
            }
        }
    }

    int g4 = lane >> 2, t4 = lane & 3;
    int r0 = mw * 16 + g4;
    #pragma unroll
    for (int n8 = 0; n8 < 10; n8++) {
        int eo = nh * 160 + nw * 80 + n8 * 8 + t4 * 2;
        if (eo < 300) {
            float bi = conv_b[eo];
            g_R[(size_t)(s * 48 + r0) * 300 + eo]     = tanhf(acc[n8][0] + bi);
            g_R[(size_t)(s * 48 + r0 + 8) * 300 + eo] = tanhf(acc[n8][2] + bi);
        }
        if (eo + 1 < 300) {
            float bi = conv_b[eo + 1];
            g_R[(size_t)(s * 48 + r0) * 300 + eo + 1]     = tanhf(acc[n8][1] + bi);
            g_R[(size_t)(s * 48 + r0 + 8) * 300 + eo + 1] = tanhf(acc[n8][3] + bi);
        }
    }
}

// ---------------------------------------------------------------------------
// joint_tc: HMMA fp16 3-term fused joint GEMM + atomic masked max.
// grid (18, 3, 64): x = it*3 + fc, y = jt, z = b. 256 threads (8 warps 4Mx2N).
// ---------------------------------------------------------------------------
#define AST 72
#define BST 72
#define JST 116
#define OF_BH 0
#define OF_BL 16384
#define OF_AH 32768
#define OF_AL 51200
#define OF_R1 69632
#define OF_R2 79360
#define SMB_TOTAL 98816

__global__ __launch_bounds__(256) void joint_tc(
    const int* __restrict__ q1_len, const int* __restrict__ q2_len)
{
    int xf = blockIdx.x;
    int it = xf / 3, fc = xf % 3;
    int jt = blockIdx.y, b = blockIdx.z;
    int l1 = q1_len[b], l2 = q2_len[b];
    if (it * 8 >= l1 || jt * 16 >= l2) return;

    extern __shared__ char smc[];
    __half* sBh = (__half*)(smc + OF_BH);
    __half* sBl = (__half*)(smc + OF_BL);
    __half* sAh = (__half*)(smc + OF_AH);
    __half* sAl = (__half*)(smc + OF_AL);
    float* r1s = (float*)(smc + OF_R1);   // [8][304]
    float* r2s = (float*)(smc + OF_R2);   // [16][304]
    float* smJ = (float*)smc;             // epilogue reuse

    int tid = threadIdx.x;
    int warp = tid >> 5, lane = tid & 31;
    int nw = warp & 1, mw = warp >> 1;

    {
        const float4* R1 = (const float4*)(g_R + (size_t)(b * 48 + it * 8) * 300);
        const float4* R2 = (const float4*)(g_R + (size_t)((64 + b) * 48 + jt * 16) * 300);
        for (int i = tid; i < 8 * 75; i += 256) {
            int r = i / 75, c = i - r * 75;
            ((float4*)(r1s + r * 304))[c] = R1[r * 75 + c];
        }
        for (int i = tid; i < 16 * 75; i += 256) {
            int r = i / 75, c = i - r * 75;
            ((float4*)(r2s + r * 304))[c] = R2[r * 75 + c];
        }
    }

    float acc[2][7][4];
    #pragma unroll
    for (int mi = 0; mi < 2; mi++)
        #pragma unroll
        for (int ni = 0; ni < 7; ni++)
            #pragma unroll
            for (int v = 0; v < 4; v++) acc[mi][ni][v] = 0.f;

    uint32_t sbase = smem_u32(smc);
    int arow = mw * 32 + (lane & 15);
    int acol = (lane >> 4) << 3;
    uint32_t aAh0 = sbase + OF_AH + (uint32_t)(arow * AST + acol) * 2;
    uint32_t aAh1 = aAh0 + 16 * AST * 2;
    uint32_t aAl0 = sbase + OF_AL + (uint32_t)(arow * AST + acol) * 2;
    uint32_t aAl1 = aAl0 + 16 * AST * 2;
    int brow = nw * 56 + (lane & 7);
    int bcol = lane & 8;
    uint32_t aBh = sbase + OF_BH + (uint32_t)(brow * BST + bcol) * 2;
    uint32_t aBl = sbase + OF_BL + (uint32_t)(brow * BST + bcol) * 2;

    int fp_ = tid >> 1, fhalf = tid & 1;
    const float* r1p = r1s + (fp_ >> 4) * 304;
    const float* r2p = r2s + (fp_ & 15) * 304;
    __half2* fdh = (__half2*)(sAh + fp_ * AST + fhalf * 32);
    __half2* fdl = (__half2*)(sAl + fp_ * AST + fhalf * 32);

    for (int c = 0; c < 10; c++) {
        __syncthreads();
        {
            const uint4* srch = g_W4h + (size_t)(fc * 10 + c) * 896;
            const uint4* srcl = g_W4l + (size_t)(fc * 10 + c) * 896;
            for (int i = tid; i < 896; i += 256) {
                int n = i >> 3, kk = i & 7;
                *(uint4*)(sBh + n * BST + kk * 8) = srch[i];
                *(uint4*)(sBl + n * BST + kk * 8) = srcl[i];
            }
        }
        {
            int kb = c * 64 + fhalf * 32;
            #pragma unroll
            for (int m = 0; m < 16; m++) {
                int e = kb + 2 * m;
                float v0, v1;
                if (e < 300)      { v0 = fabsf(r1p[e] - r2p[e]);      v1 = fabsf(r1p[e + 1] - r2p[e + 1]); }
                else if (e < 600) { v0 = r1p[e - 300] * r2p[e - 300]; v1 = r1p[e - 299] * r2p[e - 299]; }
                else              { v0 = 0.f; v1 = 0.f; }
                __half h0 = __float2half_rn(v0), h1 = __float2half_rn(v1);
                fdh[m] = __halves2half2(h0, h1);
                fdl[m] = __halves2half2(__float2half_rn(v0 - __half2float(h0)),
                                        __float2half_rn(v1 - __half2float(h1)));
            }
        }
        __syncthreads();

        #pragma unroll
        for (int ks = 0; ks < 4; ks++) {
            uint32_t k2 = (uint32_t)(ks * 16) * 2;
            uint32_t ah[2][4], al[2][4], bh[7][2], bl[7][2];
            LDSM4(ah[0], aAh0 + k2);
            LDSM4(ah[1], aAh1 + k2);
            #pragma unroll
            for (int n8 = 0; n8 < 7; n8++) LDSM2(bh[n8], aBh + (uint32_t)(n8 * 8 * BST) * 2 + k2);
            #pragma unroll
            for (int mi = 0; mi < 2; mi++)
                #pragma unroll
                for (int ni = 0; ni < 7; ni++) MMA16816(acc[mi][ni], ah[mi], bh[ni]);
            LDSM4(al[0], aAl0 + k2);
            LDSM4(al[1], aAl1 + k2);
            #pragma unroll
            for (int mi = 0; mi < 2; mi++)
                #pragma unroll
                for (int ni = 0; ni < 7; ni++) MMA16816(acc[mi][ni], al[mi], bh[ni]);
            #pragma unroll
            for (int n8 = 0; n8 < 7; n8++) LDSM2(bl[n8], aBl + (uint32_t)(n8 * 8 * BST) * 2 + k2);
            #pragma unroll
            for (int mi = 0; mi < 2; mi++)
                #pragma unroll
                for (int ni = 0; ni < 7; ni++) MMA16816(acc[mi][ni], ah[mi], bl[ni]);
        }
    }
    __syncthreads();

    {
        int r0 = mw * 32 + (lane >> 2);
        int c0 = nw * 56 + (lane & 3) * 2;
        #pragma unroll
        for (int mi = 0; mi < 2; mi++)
            #pragma unroll
            for (int ni = 0; ni < 7; ni++) {
                int r = r0 + mi * 16, cc = c0 + ni * 8;
                smJ[r * JST + cc]           = acc[mi][ni][0];
                smJ[r * JST + cc + 1]       = acc[mi][ni][1];
                smJ[(r + 8) * JST + cc]     = acc[mi][ni][2];
                smJ[(r + 8) * JST + cc + 1] = acc[mi][ni][3];
            }
    }
    __syncthreads();

    int fbase = fc * 112;
    int flim = min(112, 300 - fbase);
    int icnt = min(8, l1 - it * 8);
    int jcnt = min(16, l2 - jt * 16);

    for (int idx = tid; idx < icnt * flim; idx += 256) {
        int i = idx / flim, f = idx - i * flim;
        float v = smJ[(i * 16) * JST + f];
        for (int j = 1; j < jcnt; j++) v = fmaxf(v, smJ[(i * 16 + j) * JST + f]);
        int ig = it * 8 + i, fg = fbase + f;
        atomicMax(&g_Su[(size_t)(b * 48 + ig) * 304 + fg], enc_f(v));
    }
    for (int idx = tid; idx < jcnt * flim; idx += 256) {
        int j = idx / flim, f = idx - j * flim;
        float v = smJ[j * JST + f];
        for (int i = 1; i < icnt; i++) v = fmaxf(v, smJ[(i * 16 + j) * JST + f]);
        int jg = jt * 16 + j, fg = fbase + f;
        atomicMax(&g_Su[S2_OFF + (size_t)(b * 48 + jg) * 304 + fg], enc_f(v));
    }
}

// ---------------------------------------------------------------------------
// pool: decode s + tanh+bias ; attention softmax ; h -> g_H
// ---------------------------------------------------------------------------
__global__ __launch_bounds__(256) void pool_kernel(
    const int* __restrict__ q1_len, const int* __restrict__ q2_len,
    const float* __restrict__ att_w, const float* __restrict__ att_b,
    const float* __restrict__ fc0_b)
{
    int side = blockIdx.x, b = blockIdx.y;
    int l1 = q1_len[b], l2 = q2_len[b];
    int len = side ? l2 : l1;
    const unsigned* Sb = g_Su + (size_t)side * S2_OFF + (size_t)b * 48 * 304;

    extern __shared__ float sm[];
    float* sv = sm;              // [48][301]
    float* lg = sv + 48 * 301;   // [48]
    int tid = threadIdx.x;

    for (int idx = tid; idx < len * 300; idx += 256) {
        int l = idx / 300, f = idx - l * 300;
        sv[l * 301 + f] = tanhf(dec_f(Sb[(size_t)l * 304 + f]) + fc0_b[f]);
    }
    __syncthreads();

    int lane = tid & 31, warp = tid >> 5;
    const float* Rbase = g_R + (size_t)(side * 64 + b) * 48 * 300;
    for (int l = warp; l < len; l += 8) {
        float a = 0.f;
        for (int e = lane; e < 300; e += 32) {
            a += att_w[e]       * Rbase[l * 300 + e];
            a += att_w[300 + e] * sv[l * 301 + e];
        }
        #pragma unroll
        for (int d = 16; d; d >>= 1) a += __shfl_xor_sync(0xffffffffu, a, d);
        if (lane == 0) lg[l] = a + att_b[0];
    }
    __syncthreads();

    if (warp == 0) {
        float v0 = (lane < len) ? lg[lane] : NEGV;
        float v1 = (lane + 32 < len) ? lg[lane + 32] : NEGV;
        float mx = fmaxf(v0, v1);
        #pragma unroll
        for (int d = 16; d; d >>= 1) mx = fmaxf(mx, __shfl_xor_sync(0xffffffffu, mx, d));
        float e0 = (lane < len) ? expf(v0 - mx) : 0.f;
        float e1 = (lane + 32 < len) ? expf(v1 - mx) : 0.f;
        float s = e0 + e1;
        #pragma unroll
        for (int d = 16; d; d >>= 1) s += __shfl_xor_sync(0xffffffffu, s, d);
        float inv = 1.f / s;
        if (lane < len) lg[lane] = e0 * inv;
        if (lane + 32 < len) lg[lane + 32] = e1 * inv;
    }
    __syncthreads();

    for (int f = tid; f < 300; f += 256) {
        float h = 0.f;
        for (int l = 0; l < len; l++) h += lg[l] * sv[l * 301 + f];
        g_H[b * 600 + side * 300 + f] = h;
    }
}

// ---------------------------------------------------------------------------
// head1: jv = tanh(H @ fc1_w^T + b). grid (64, 5), block 256.
// ---------------------------------------------------------------------------
__global__ __launch_bounds__(256) void head1_kernel(
    const float* __restrict__ fc1_w, const float* __restrict__ fc1_b)
{
    __shared__ float Hs[600];
    __shared__ float part[256];
    int b = blockIdx.x, fb = blockIdx.y;
    int tid = threadIdx.x;
    for (int i = tid; i < 600; i += 256) Hs[i] = g_H[b * 600 + i];
    __syncthreads();
    int fl = tid >> 2, seg = tid & 3;
    int f = fb * 60 + fl;
    float acc = 0.f;
    if (fl < 60) {
        const float* w = fc1_w + (size_t)f * 600 + seg * 150;
        const float* h = Hs + seg * 150;
        #pragma unroll 6
        for (int k = 0; k < 150; k++) acc += h[k] * w[k];
    }
    part[tid] = acc;
    __syncthreads();
    if (seg == 0 && fl < 60) {
        float s = part[tid] + part[tid + 1] + part[tid + 2] + part[tid + 3];
        g_J[b * 300 + f] = tanhf(s + fc1_b[f]);
    }
}

// head2: out = jv @ fc2_w^T + b. grid 64, block 64.
__global__ __launch_bounds__(64) void head2_kernel(
    const float* __restrict__ fc2_w, const float* __restrict__ fc2_b,
    float* __restrict__ out)
{
    int b = blockIdx.x, tid = threadIdx.x;
    int c = tid >> 5, lane = tid & 31;
    float acc = 0.f;
    for (int f = lane; f < 300; f += 32)
        acc += g_J[b * 300 + f] * fc2_w[c * 300 + f];
    #pragma unroll
    for (int d = 16; d; d >>= 1) acc += __shfl_xor_sync(0xffffffffu, acc, d);
    if (lane == 0) out[b * 2 + c] = acc + fc2_b[c];
}

// ---------------------------------------------------------------------------
extern "C" void kernel_launch(void* const* d_in, const int* in_sizes, int n_in,
                              void* d_out, int out_size)
{
    const int*   q1     = (const int*)d_in[0];
    const int*   q2     = (const int*)d_in[1];
    const int*   q1_len = (const int*)d_in[2];
    const int*   q2_len = (const int*)d_in[3];
    const float* emb    = (const float*)d_in[4];
    const float* conv_w = (const float*)d_in[5];
    const float* conv_b = (const float*)d_in[6];
    const float* fc0_w  = (const float*)d_in[7];
    const float* fc0_b  = (const float*)d_in[8];
    const float* fc1_w  = (const float*)d_in[9];
    const float* fc1_b  = (const float*)d_in[10];
    const float* fc2_w  = (const float*)d_in[11];
    const float* fc2_b  = (const float*)d_in[12];
    const float* att_w  = (const float*)d_in[13];
    const float* att_b  = (const float*)d_in[14];
    float* out = (float*)d_out;

    const int smC = 48 * 301 * 4 + 48 * 4;

    cudaFuncSetAttribute(encode_tc,   cudaFuncAttributeMaxDynamicSharedMemorySize, SME_TOTAL);
    cudaFuncSetAttribute(joint_tc,    cudaFuncAttributeMaxDynamicSharedMemorySize, SMB_TOTAL);
    cudaFuncSetAttribute(pool_kernel, cudaFuncAttributeMaxDynamicSharedMemorySize, smC);

    prep_w<<<dim3(30, 112), 64>>>(fc0_w);
    prep_cw<<<dim3(3, 320), 320>>>(conv_w);
    init_s<<<7296, 256>>>();
    encode_tc<<<dim3(128, 2), 192, SME_TOTAL>>>(q1, q2, emb, conv_b);
    joint_tc<<<dim3(18, 3, 64), 256, SMB_TOTAL>>>(q1_len, q2_len);
    pool_kernel<<<dim3(2, 64), 256, smC>>>(q1_len, q2_len, att_w, att_b, fc0_b);
    head1_kernel<<<dim3(64, 5), 256>>>(fc1_w, fc1_b);
    head2_kernel<<<64, 64>>>(fc2_w, fc2_b, out);
    (void)in_sizes; (void)n_in; (void)out_size;
}